// round 7
// baseline (speedup 1.0000x reference)
#include <cuda_runtime.h>
#include <cuda_fp16.h>
#include <math.h>

#define NNODES 100000
#define NEDGES 1600000
#define FDIM   128

// ---------------- scratch ----------------
__device__ __half g_hh[NNODES * FDIM];   // GEMM output in fp16 (gather path)
__device__ float  g_feat[NNODES * FDIM]; // layer-1 activations (fp32, GEMM2 input)
__device__ float  g_as[NNODES * 4];
__device__ float  g_ad[NNODES * 4];
__device__ int    g_cnt[NNODES];
__device__ int    g_rp[NNODES + 1];
__device__ int    g_cursor[NNODES];
__device__ int    g_bsum[64];
__device__ int    g_csr[NEDGES];

// ---------------- f32x2 helpers (sm_103a packed fp32) ----------------
__device__ __forceinline__ unsigned long long pack2(float x) {
    unsigned long long r;
    asm("mov.b64 %0, {%1, %1};" : "=l"(r) : "r"(__float_as_uint(x)));
    return r;
}
#define FMA2(d, a, b) asm("fma.rn.f32x2 %0, %1, %2, %0;" : "+l"(d) : "l"(a), "l"(b))
__device__ __forceinline__ void unpack2(unsigned long long p, float& lo, float& hi) {
    asm("mov.b64 {%0, %1}, %2;" : "=f"(lo), "=f"(hi) : "l"(p));
}

// ---------------- GEMM + fused alpha epilogue; fp16 feature output ----------------
template <int H>
__global__ void gemm_alpha_kernel(const float* __restrict__ A,
                                  const float* __restrict__ W,
                                  __half* __restrict__ hh, int M,
                                  const float* __restrict__ a_src,
                                  const float* __restrict__ a_dst,
                                  float* __restrict__ as_, float* __restrict__ ad_) {
    __shared__ float As[128 * 66];
    int tid  = threadIdx.x;
    int row0 = blockIdx.x * 64;
    int tx = tid & 31;
    int ty = tid >> 5;

    #pragma unroll
    for (int i = 0; i < 8; i++) {
        int idx = tid + 256 * i;
        int r   = idx >> 5;
        int c4  = idx & 31;
        float4 v = make_float4(0.f, 0.f, 0.f, 0.f);
        if (row0 + r < M) v = ((const float4*)A)[(size_t)(row0 + r) * 32 + c4];
        int c = c4 * 4;
        As[(c + 0) * 66 + r] = v.x;
        As[(c + 1) * 66 + r] = v.y;
        As[(c + 2) * 66 + r] = v.z;
        As[(c + 3) * 66 + r] = v.w;
    }
    __syncthreads();

    unsigned long long acc[4][4];
    #pragma unroll
    for (int p = 0; p < 4; p++)
        #pragma unroll
        for (int c = 0; c < 4; c++) acc[p][c] = 0ull;

    const float* asbase = As + ty * 8;
    #pragma unroll 4
    for (int k = 0; k < 128; k++) {
        float4 w = __ldg(&((const float4*)(W + k * 128))[tx]);
        unsigned long long w0 = pack2(w.x), w1 = pack2(w.y),
                           w2 = pack2(w.z), w3 = pack2(w.w);
        const unsigned long long* ap =
            (const unsigned long long*)(asbase + k * 66);
        unsigned long long a0 = ap[0], a1 = ap[1], a2 = ap[2], a3 = ap[3];
        FMA2(acc[0][0], a0, w0); FMA2(acc[0][1], a0, w1);
        FMA2(acc[0][2], a0, w2); FMA2(acc[0][3], a0, w3);
        FMA2(acc[1][0], a1, w0); FMA2(acc[1][1], a1, w1);
        FMA2(acc[1][2], a1, w2); FMA2(acc[1][3], a1, w3);
        FMA2(acc[2][0], a2, w0); FMA2(acc[2][1], a2, w1);
        FMA2(acc[2][2], a2, w2); FMA2(acc[2][3], a2, w3);
        FMA2(acc[3][0], a3, w0); FMA2(acc[3][1], a3, w1);
        FMA2(acc[3][2], a3, w2); FMA2(acc[3][3], a3, w3);
    }

    float4 s4 = ((const float4*)a_src)[tx];
    float4 d4 = ((const float4*)a_dst)[tx];
    const int G = 32 / H;

    #pragma unroll
    for (int p = 0; p < 4; p++) {
        float lo[4], hi[4];
        #pragma unroll
        for (int c = 0; c < 4; c++) unpack2(acc[p][c], lo[c], hi[c]);

        #pragma unroll
        for (int half = 0; half < 2; half++) {
            float* v = half ? hi : lo;
            int row = row0 + ty * 8 + p * 2 + half;
            bool ok = row < M;
            if (ok) {
                __half2 h01 = __floats2half2_rn(v[0], v[1]);
                __half2 h23 = __floats2half2_rn(v[2], v[3]);
                uint2 pk;
                pk.x = *(unsigned int*)&h01;
                pk.y = *(unsigned int*)&h23;
                ((uint2*)hh)[(size_t)row * 32 + tx] = pk;
            }
            float s = v[0] * s4.x + v[1] * s4.y + v[2] * s4.z + v[3] * s4.w;
            float d = v[0] * d4.x + v[1] * d4.y + v[2] * d4.z + v[3] * d4.w;
            #pragma unroll
            for (int off = G / 2; off > 0; off >>= 1) {
                s += __shfl_xor_sync(0xffffffffu, s, off);
                d += __shfl_xor_sync(0xffffffffu, d, off);
            }
            if (ok && (tx & (G - 1)) == 0) {
                int hd = tx / G;
                as_[row * H + hd] = s;
                ad_[row * H + hd] = d;
            }
        }
    }
}

// ---------------- CSR construction ----------------
__global__ void count_kernel(const int* __restrict__ dst, int* __restrict__ cnt) {
    int e = blockIdx.x * blockDim.x + threadIdx.x;
    if (e < NEDGES) atomicAdd(&cnt[dst[e]], 1);
}

__global__ void scan_local_kernel(const int* __restrict__ cnt,
                                  int* __restrict__ excl, int* __restrict__ bsum) {
    __shared__ int sh[512];
    int t = threadIdx.x;
    int base = blockIdx.x * 4096 + t * 8;
    int v[8];
    int run = 0;
    #pragma unroll
    for (int j = 0; j < 8; j++) {
        int c = (base + j < NNODES) ? cnt[base + j] : 0;
        v[j] = run;
        run += c;
    }
    sh[t] = run;
    __syncthreads();
    for (int off = 1; off < 512; off <<= 1) {
        int x = (t >= off) ? sh[t - off] : 0;
        __syncthreads();
        sh[t] += x;
        __syncthreads();
    }
    int excl_t = sh[t] - run;
    if (t == 511) bsum[blockIdx.x] = sh[511];
    #pragma unroll
    for (int j = 0; j < 8; j++)
        if (base + j < NNODES) excl[base + j] = excl_t + v[j];
}

__global__ void scan_add_kernel(const int* __restrict__ excl, const int* __restrict__ bsum,
                                int* __restrict__ rp, int* __restrict__ cursor, int nb) {
    int i = blockIdx.x * blockDim.x + threadIdx.x;
    if (i <= NNODES) {
        int blk = i >> 12;
        int base = 0;
        for (int j = 0; j < nb; j++)
            if (j < blk) base += bsum[j];
        if (i < NNODES) {
            int v = excl[i] + base;
            rp[i] = v;
            cursor[i] = v;
        } else {
            rp[NNODES] = NEDGES;
        }
    }
}

__global__ void scatter_kernel(const int* __restrict__ src, const int* __restrict__ dst,
                               int* __restrict__ cursor, int* __restrict__ csr) {
    int e = blockIdx.x * blockDim.x + threadIdx.x;
    if (e >= NEDGES) return;
    int p = atomicAdd(&cursor[dst[e]], 1);
    csr[p] = src[e];
}

// ---------------- fused aggregation: 2 dst nodes per warp, 16 lanes each ----------------
// Each lane owns 8 fp16 channels (uint4 = 16B gather). One LDG.128 warp-inst
// serves two edges (one per half-warp). Predicated masking handles unequal degrees.
template <int H, bool ELU>
__global__ void __launch_bounds__(256, 4)
fused_agg_kernel(const int* __restrict__ rowp, const int* __restrict__ csr,
                 const float* __restrict__ as_, const float* __restrict__ ad_,
                 const __half* __restrict__ hfeat,
                 const float* __restrict__ bias,
                 float* __restrict__ outp) {
    int warp = (blockIdx.x * blockDim.x + threadIdx.x) >> 5;
    int lane = threadIdx.x & 31;
    int d0 = warp * 2;
    if (d0 >= NNODES) return;
    int half = lane >> 4;      // 0 or 1: which dst node this lane serves
    int hl   = lane & 15;      // lane within half
    int d = d0 + half;         // NNODES is even -> always valid

    const int C = 128 / H;
    const int myh = (hl * 8) / C;   // head owning channels hl*8..hl*8+7
    float adm = ad_[d * H + myh];
    const uint4* hf4 = (const uint4*)hfeat;   // 16 uint4 per 128-ch row

    int beg = rowp[d], end = rowp[d + 1];
    int n = end - beg;
    int nmax = max(n, __shfl_xor_sync(0xffffffffu, n, 16));
    int last = max(end - 1, 0);

    // self loop
    float sv = as_[d * H + myh] + adm;
    sv = sv >= 0.f ? sv : 0.2f * sv;
    float ev = __expf(sv);
    float den = ev;
    float acc[8];
    {
        uint4 rs = hf4[(size_t)d * 16 + hl];
        float2 p0 = __half22float2(*(__half2*)&rs.x);
        float2 p1 = __half22float2(*(__half2*)&rs.y);
        float2 p2 = __half22float2(*(__half2*)&rs.z);
        float2 p3 = __half22float2(*(__half2*)&rs.w);
        acc[0] = p0.x * ev; acc[1] = p0.y * ev;
        acc[2] = p1.x * ev; acc[3] = p1.y * ev;
        acc[4] = p2.x * ev; acc[5] = p2.y * ev;
        acc[6] = p3.x * ev; acc[7] = p3.y * ev;
    }

    int j = 0;
    for (; j + 3 < nmax; j += 4) {
        int i0 = min(beg + j + 0, last);
        int i1 = min(beg + j + 1, last);
        int i2 = min(beg + j + 2, last);
        int i3 = min(beg + j + 3, last);
        int s0 = csr[i0], s1 = csr[i1], s2 = csr[i2], s3 = csr[i3];
        float v0 = as_[s0 * H + myh];
        float v1 = as_[s1 * H + myh];
        float v2 = as_[s2 * H + myh];
        float v3 = as_[s3 * H + myh];
        uint4 r0 = hf4[(size_t)s0 * 16 + hl];
        uint4 r1 = hf4[(size_t)s1 * 16 + hl];
        uint4 r2 = hf4[(size_t)s2 * 16 + hl];
        uint4 r3 = hf4[(size_t)s3 * 16 + hl];
        v0 += adm; v1 += adm; v2 += adm; v3 += adm;
        v0 = v0 >= 0.f ? v0 : 0.2f * v0;
        v1 = v1 >= 0.f ? v1 : 0.2f * v1;
        v2 = v2 >= 0.f ? v2 : 0.2f * v2;
        v3 = v3 >= 0.f ? v3 : 0.2f * v3;
        float e0 = (j + 0 < n) ? __expf(v0) : 0.f;
        float e1 = (j + 1 < n) ? __expf(v1) : 0.f;
        float e2 = (j + 2 < n) ? __expf(v2) : 0.f;
        float e3 = (j + 3 < n) ? __expf(v3) : 0.f;
        den += (e0 + e1) + (e2 + e3);
        #pragma unroll
        for (int k = 0; k < 4; k++) {
            uint4 r = k == 0 ? r0 : k == 1 ? r1 : k == 2 ? r2 : r3;
            float e = k == 0 ? e0 : k == 1 ? e1 : k == 2 ? e2 : e3;
            float2 p0 = __half22float2(*(__half2*)&r.x);
            float2 p1 = __half22float2(*(__half2*)&r.y);
            float2 p2 = __half22float2(*(__half2*)&r.z);
            float2 p3 = __half22float2(*(__half2*)&r.w);
            acc[0] += p0.x * e; acc[1] += p0.y * e;
            acc[2] += p1.x * e; acc[3] += p1.y * e;
            acc[4] += p2.x * e; acc[5] += p2.y * e;
            acc[6] += p3.x * e; acc[7] += p3.y * e;
        }
    }
    for (; j < nmax; j++) {
        int i0 = min(beg + j, last);
        int s0 = csr[i0];
        float v0 = as_[s0 * H + myh] + adm;
        v0 = v0 >= 0.f ? v0 : 0.2f * v0;
        float e0 = (j < n) ? __expf(v0) : 0.f;
        uint4 r0 = hf4[(size_t)s0 * 16 + hl];
        float2 p0 = __half22float2(*(__half2*)&r0.x);
        float2 p1 = __half22float2(*(__half2*)&r0.y);
        float2 p2 = __half22float2(*(__half2*)&r0.z);
        float2 p3 = __half22float2(*(__half2*)&r0.w);
        den += e0;
        acc[0] += p0.x * e0; acc[1] += p0.y * e0;
        acc[2] += p1.x * e0; acc[3] += p1.y * e0;
        acc[4] += p2.x * e0; acc[5] += p2.y * e0;
        acc[6] += p3.x * e0; acc[7] += p3.y * e0;
    }

    float inv = 1.f / (den + 1e-16f);
    float4 b0 = ((const float4*)bias)[hl * 2];
    float4 b1 = ((const float4*)bias)[hl * 2 + 1];
    float o[8];
    o[0] = acc[0] * inv + b0.x; o[1] = acc[1] * inv + b0.y;
    o[2] = acc[2] * inv + b0.z; o[3] = acc[3] * inv + b0.w;
    o[4] = acc[4] * inv + b1.x; o[5] = acc[5] * inv + b1.y;
    o[6] = acc[6] * inv + b1.z; o[7] = acc[7] * inv + b1.w;
    if (ELU) {
        #pragma unroll
        for (int k = 0; k < 8; k++) o[k] = o[k] > 0.f ? o[k] : expm1f(o[k]);
    }
    ((float4*)outp)[(size_t)d * 32 + hl * 2]     = make_float4(o[0], o[1], o[2], o[3]);
    ((float4*)outp)[(size_t)d * 32 + hl * 2 + 1] = make_float4(o[4], o[5], o[6], o[7]);
}

// ---------------- launch ----------------
extern "C" void kernel_launch(void* const* d_in, const int* in_sizes, int n_in,
                              void* d_out, int out_size) {
    const float* x      = (const float*)d_in[0];
    const int*   ei     = (const int*)d_in[1];
    const float* W1     = (const float*)d_in[2];
    const float* a_src1 = (const float*)d_in[3];
    const float* a_dst1 = (const float*)d_in[4];
    const float* b1     = (const float*)d_in[5];
    const float* W2     = (const float*)d_in[6];
    const float* a_src2 = (const float*)d_in[7];
    const float* a_dst2 = (const float*)d_in[8];
    const float* b2     = (const float*)d_in[9];
    float* out = (float*)d_out;

    const int* src = ei;
    const int* dst = ei + NEDGES;

    __half* p_hh;
    float *p_feat, *p_as, *p_ad;
    int *p_cnt, *p_rp, *p_cursor, *p_bsum, *p_csr;
    cudaGetSymbolAddress((void**)&p_hh,     g_hh);
    cudaGetSymbolAddress((void**)&p_feat,   g_feat);
    cudaGetSymbolAddress((void**)&p_as,     g_as);
    cudaGetSymbolAddress((void**)&p_ad,     g_ad);
    cudaGetSymbolAddress((void**)&p_cnt,    g_cnt);
    cudaGetSymbolAddress((void**)&p_rp,     g_rp);
    cudaGetSymbolAddress((void**)&p_cursor, g_cursor);
    cudaGetSymbolAddress((void**)&p_bsum,   g_bsum);
    cudaGetSymbolAddress((void**)&p_csr,    g_csr);

    static cudaStream_t s_side = nullptr;
    static cudaEvent_t  ev_fork = nullptr, ev_join = nullptr;
    if (s_side == nullptr) {
        cudaStreamCreateWithFlags(&s_side, cudaStreamNonBlocking);
        cudaEventCreateWithFlags(&ev_fork, cudaEventDisableTiming);
        cudaEventCreateWithFlags(&ev_join, cudaEventDisableTiming);
    }

    const int NT = 256;
    int gemm_blocks  = (NNODES + 63) / 64;
    int pair_warps   = ((NNODES + 1) / 2 * 32 + NT - 1) / NT;
    int node1_blocks = (NNODES + 1 + NT - 1) / NT;
    int edge_blocks  = (NEDGES + NT - 1) / NT;
    int scan_blocks  = (NNODES + 4095) / 4096;

    // fork: CSR build on side stream (submitted first so ncu -s lands on hot kernels)
    cudaEventRecord(ev_fork, 0);
    cudaStreamWaitEvent(s_side, ev_fork, 0);

    cudaMemsetAsync(p_cnt, 0, NNODES * sizeof(int), s_side);
    count_kernel<<<edge_blocks, NT, 0, s_side>>>(dst, p_cnt);
    scan_local_kernel<<<scan_blocks, 512, 0, s_side>>>(p_cnt, p_cnt, p_bsum);
    scan_add_kernel<<<node1_blocks, NT, 0, s_side>>>(p_cnt, p_bsum, p_rp, p_cursor, scan_blocks);
    scatter_kernel<<<edge_blocks, NT, 0, s_side>>>(src, dst, p_cursor, p_csr);
    cudaEventRecord(ev_join, s_side);

    // main stream: GEMM1 (+alpha), concurrent with CSR build
    gemm_alpha_kernel<4><<<gemm_blocks, NT>>>(x, W1, p_hh, NNODES,
                                              a_src1, a_dst1, p_as, p_ad);
    cudaStreamWaitEvent(0, ev_join, 0);

    fused_agg_kernel<4, true><<<pair_warps, NT>>>(p_rp, p_csr, p_as, p_ad, p_hh, b1, p_feat);

    gemm_alpha_kernel<1><<<gemm_blocks, NT>>>(p_feat, W2, p_hh, NNODES,
                                              a_src2, a_dst2, p_as, p_ad);
    fused_agg_kernel<1, false><<<pair_warps, NT>>>(p_rp, p_csr, p_as, p_ad, p_hh, b2, out);
}

// round 9
// speedup vs baseline: 1.3002x; 1.3002x over previous
#include <cuda_runtime.h>
#include <cuda_fp16.h>
#include <cuda_bf16.h>
#include <math.h>
#include <stdint.h>

#define NNODES 100000
#define NEDGES 1600000
#define FDIM   128

// ---------------- scratch ----------------
__device__ __half g_hh[NNODES * FDIM];   // GEMM output in fp16 (gather path)
__device__ float  g_feat[NNODES * FDIM]; // layer-1 activations (fp32, GEMM2 input)
__device__ float  g_as[NNODES * 4];
__device__ float  g_ad[NNODES * 4];
__device__ int    g_cnt[NNODES];
__device__ int    g_rp[NNODES + 1];
__device__ int    g_cursor[NNODES];
__device__ int    g_bsum[64];
__device__ int    g_csr[NEDGES];
// W as Bt[n][k] bf16 hi/lo images (row-major, k contiguous)
__device__ __nv_bfloat16 g_bhi1[16384], g_blo1[16384];
__device__ __nv_bfloat16 g_bhi2[16384], g_blo2[16384];

// ---------------- helpers ----------------
__device__ __forceinline__ void bsplit(float2 f, uint32_t& hi, uint32_t& lo) {
    __nv_bfloat16 h0 = __float2bfloat16(f.x), h1 = __float2bfloat16(f.y);
    __nv_bfloat16 l0 = __float2bfloat16(f.x - __bfloat162float(h0));
    __nv_bfloat16 l1 = __float2bfloat16(f.y - __bfloat162float(h1));
    hi = ((uint32_t)__bfloat16_as_ushort(h1) << 16) | (uint32_t)__bfloat16_as_ushort(h0);
    lo = ((uint32_t)__bfloat16_as_ushort(l1) << 16) | (uint32_t)__bfloat16_as_ushort(l0);
}

#define MMA_BF16(c, a, b0, b1) \
    asm volatile("mma.sync.aligned.m16n8k16.row.col.f32.bf16.bf16.f32 " \
        "{%0,%1,%2,%3}, {%4,%5,%6,%7}, {%8,%9}, {%0,%1,%2,%3};" \
        : "+f"((c)[0]), "+f"((c)[1]), "+f"((c)[2]), "+f"((c)[3]) \
        : "r"((a)[0]), "r"((a)[1]), "r"((a)[2]), "r"((a)[3]), "r"(b0), "r"(b1))

// ---------------- prep: W[k][n] -> Bt[n][k] bf16 hi/lo ----------------
__global__ void prep_w_kernel(const float* __restrict__ W1, const float* __restrict__ W2,
                              __nv_bfloat16* __restrict__ bh1, __nv_bfloat16* __restrict__ bl1,
                              __nv_bfloat16* __restrict__ bh2, __nv_bfloat16* __restrict__ bl2) {
    int idx = blockIdx.x * blockDim.x + threadIdx.x;
    if (idx >= 2 * 16384) return;
    const float* W = (idx < 16384) ? W1 : W2;
    __nv_bfloat16* bh = (idx < 16384) ? bh1 : bh2;
    __nv_bfloat16* bl = (idx < 16384) ? bl1 : bl2;
    int e = idx & 16383;
    int n = e >> 7, k = e & 127;
    float v = W[k * 128 + n];
    __nv_bfloat16 h = __float2bfloat16(v);
    __nv_bfloat16 l = __float2bfloat16(v - __bfloat162float(h));
    bh[e] = h;   // e == n*128 + k
    bl[e] = l;
}

// ---------------- bf16x3 HMMA GEMM + fused alpha epilogue ----------------
// hh[M,128] fp16 = A[M,128] @ W ; D = Ahi*Bhi + Ahi*Blo + Alo*Bhi (fp32 accum).
// 256 threads, 8 warps; warp w owns rows [blk*128 + w*16, +16), all 128 cols.
// smem: Bt hi/lo padded stride 136 (bank-conflict-free fragment loads) + avec.
#define SB_STRIDE 136
#define SB_BYTES  (128 * SB_STRIDE * 2)       // 34816 per image
#define SMEM_AVEC (2 * SB_BYTES)              // 69632
#define SMEM_GTOT (SMEM_AVEC + 256 * 4)       // 70656

template <int H>
__global__ void __launch_bounds__(256)
gemm_mma_kernel(const float* __restrict__ A,
                const __nv_bfloat16* __restrict__ Bh, const __nv_bfloat16* __restrict__ Bl,
                __half* __restrict__ hh, int M,
                const float* __restrict__ a_src, const float* __restrict__ a_dst,
                float* __restrict__ as_, float* __restrict__ ad_) {
    extern __shared__ char smem[];
    __nv_bfloat16* sBh = (__nv_bfloat16*)smem;
    __nv_bfloat16* sBl = (__nv_bfloat16*)(smem + SB_BYTES);
    float* avec = (float*)(smem + SMEM_AVEC);

    int tid = threadIdx.x;
    // stage B hi/lo: 2048 uint4 each (16 uint4 per 128-elem row)
    for (int i = tid; i < 2048; i += 256) {
        int n = i >> 4, kk = (i & 15) * 8;
        uint4 vh = ((const uint4*)Bh)[i];
        uint4 vl = ((const uint4*)Bl)[i];
        *(uint4*)&sBh[n * SB_STRIDE + kk] = vh;
        *(uint4*)&sBl[n * SB_STRIDE + kk] = vl;
    }
    if (tid < 128) { avec[tid] = a_src[tid]; avec[128 + tid] = a_dst[tid]; }
    __syncthreads();

    int w = tid >> 5, lane = tid & 31;
    int g = lane >> 2, t = lane & 3;
    int rga = blockIdx.x * 128 + w * 16 + g;
    int rgb = rga + 8;
    bool oka = rga < M, okb = rgb < M;

    float acc[16][4];
    #pragma unroll
    for (int nt = 0; nt < 16; nt++)
        #pragma unroll
        for (int c = 0; c < 4; c++) acc[nt][c] = 0.f;

    const float2 z2 = make_float2(0.f, 0.f);
    #pragma unroll
    for (int ks = 0; ks < 8; ks++) {
        int kb = ks * 16;
        float2 f0 = oka ? *(const float2*)&A[(size_t)rga * 128 + kb + 2 * t]     : z2;
        float2 f1 = okb ? *(const float2*)&A[(size_t)rgb * 128 + kb + 2 * t]     : z2;
        float2 f2 = oka ? *(const float2*)&A[(size_t)rga * 128 + kb + 8 + 2 * t] : z2;
        float2 f3 = okb ? *(const float2*)&A[(size_t)rgb * 128 + kb + 8 + 2 * t] : z2;
        uint32_t ah[4], al[4];
        bsplit(f0, ah[0], al[0]);
        bsplit(f1, ah[1], al[1]);
        bsplit(f2, ah[2], al[2]);
        bsplit(f3, ah[3], al[3]);
        #pragma unroll
        for (int nt = 0; nt < 16; nt++) {
            int boff = (nt * 8 + g) * SB_STRIDE + kb + 2 * t;
            uint32_t bh0 = *(const uint32_t*)&sBh[boff];
            uint32_t bh1 = *(const uint32_t*)&sBh[boff + 8];
            uint32_t bl0 = *(const uint32_t*)&sBl[boff];
            uint32_t bl1 = *(const uint32_t*)&sBl[boff + 8];
            MMA_BF16(acc[nt], ah, bh0, bh1);
            MMA_BF16(acc[nt], ah, bl0, bl1);
            MMA_BF16(acc[nt], al, bh0, bh1);
        }
    }

    // fp16 feature stores
    #pragma unroll
    for (int nt = 0; nt < 16; nt++) {
        int c0 = nt * 8 + 2 * t;
        if (oka) {
            __half2 p = __floats2half2_rn(acc[nt][0], acc[nt][1]);
            *(uint32_t*)&hh[(size_t)rga * 128 + c0] = *(uint32_t*)&p;
        }
        if (okb) {
            __half2 p = __floats2half2_rn(acc[nt][2], acc[nt][3]);
            *(uint32_t*)&hh[(size_t)rgb * 128 + c0] = *(uint32_t*)&p;
        }
    }

    // alpha dots (quad-local reduction over t)
    const int NTH = 16 / H;
    #pragma unroll
    for (int h = 0; h < H; h++) {
        float sa = 0.f, da = 0.f, sb = 0.f, db = 0.f;
        #pragma unroll
        for (int q = 0; q < NTH; q++) {
            int nt = h * NTH + q;
            int c = nt * 8 + 2 * t;
            float w0 = avec[c], w1 = avec[c + 1];
            float u0 = avec[128 + c], u1 = avec[128 + c + 1];
            sa += acc[nt][0] * w0 + acc[nt][1] * w1;
            da += acc[nt][0] * u0 + acc[nt][1] * u1;
            sb += acc[nt][2] * w0 + acc[nt][3] * w1;
            db += acc[nt][2] * u0 + acc[nt][3] * u1;
        }
        sa += __shfl_xor_sync(0xffffffffu, sa, 1); sa += __shfl_xor_sync(0xffffffffu, sa, 2);
        da += __shfl_xor_sync(0xffffffffu, da, 1); da += __shfl_xor_sync(0xffffffffu, da, 2);
        sb += __shfl_xor_sync(0xffffffffu, sb, 1); sb += __shfl_xor_sync(0xffffffffu, sb, 2);
        db += __shfl_xor_sync(0xffffffffu, db, 1); db += __shfl_xor_sync(0xffffffffu, db, 2);
        if (t == 0) {
            if (oka) { as_[rga * H + h] = sa; ad_[rga * H + h] = da; }
            if (okb) { as_[rgb * H + h] = sb; ad_[rgb * H + h] = db; }
        }
    }
}

// ---------------- CSR construction ----------------
__global__ void count_kernel(const int* __restrict__ dst, int* __restrict__ cnt) {
    int e = blockIdx.x * blockDim.x + threadIdx.x;
    if (e < NEDGES) atomicAdd(&cnt[dst[e]], 1);
}

__global__ void scan_local_kernel(const int* __restrict__ cnt,
                                  int* __restrict__ excl, int* __restrict__ bsum) {
    __shared__ int sh[512];
    int t = threadIdx.x;
    int base = blockIdx.x * 4096 + t * 8;
    int v[8];
    int run = 0;
    #pragma unroll
    for (int j = 0; j < 8; j++) {
        int c = (base + j < NNODES) ? cnt[base + j] : 0;
        v[j] = run;
        run += c;
    }
    sh[t] = run;
    __syncthreads();
    for (int off = 1; off < 512; off <<= 1) {
        int x = (t >= off) ? sh[t - off] : 0;
        __syncthreads();
        sh[t] += x;
        __syncthreads();
    }
    int excl_t = sh[t] - run;
    if (t == 511) bsum[blockIdx.x] = sh[511];
    #pragma unroll
    for (int j = 0; j < 8; j++)
        if (base + j < NNODES) excl[base + j] = excl_t + v[j];
}

__global__ void scan_add_kernel(const int* __restrict__ excl, const int* __restrict__ bsum,
                                int* __restrict__ rp, int* __restrict__ cursor, int nb) {
    int i = blockIdx.x * blockDim.x + threadIdx.x;
    if (i <= NNODES) {
        int blk = i >> 12;
        int base = 0;
        for (int j = 0; j < nb; j++)
            if (j < blk) base += bsum[j];
        if (i < NNODES) {
            int v = excl[i] + base;
            rp[i] = v;
            cursor[i] = v;
        } else {
            rp[NNODES] = NEDGES;
        }
    }
}

__global__ void scatter_kernel(const int* __restrict__ src, const int* __restrict__ dst,
                               int* __restrict__ cursor, int* __restrict__ csr) {
    int e = blockIdx.x * blockDim.x + threadIdx.x;
    if (e >= NEDGES) return;
    int p = atomicAdd(&cursor[dst[e]], 1);
    csr[p] = src[e];
}

// ---------------- fused aggregation (R5 version: best measured) ----------------
template <int H, bool ELU>
__global__ void fused_agg_kernel(const int* __restrict__ rowp, const int* __restrict__ csr,
                                 const float* __restrict__ as_, const float* __restrict__ ad_,
                                 const __half* __restrict__ hfeat,
                                 const float* __restrict__ bias,
                                 float* __restrict__ outp) {
    int d    = (blockIdx.x * blockDim.x + threadIdx.x) >> 5;
    int lane = threadIdx.x & 31;
    if (d >= NNODES) return;
    int beg = rowp[d], end = rowp[d + 1];

    const int G = 32 / H;
    const int myh = lane / G;
    float adm = ad_[d * H + myh];
    const uint2* hf = (const uint2*)hfeat;

    float sv = as_[d * H + myh] + adm;
    sv = sv >= 0.f ? sv : 0.2f * sv;
    float ev = __expf(sv);
    float den = ev;
    uint2 rs = hf[(size_t)d * 32 + lane];
    float2 f0 = __half22float2(*(__half2*)&rs.x);
    float2 f1 = __half22float2(*(__half2*)&rs.y);
    float4 acc = make_float4(f0.x * ev, f0.y * ev, f1.x * ev, f1.y * ev);

    int i = beg;
    for (; i + 3 < end; i += 4) {
        int s0 = csr[i], s1 = csr[i + 1], s2 = csr[i + 2], s3 = csr[i + 3];
        float v0 = as_[s0 * H + myh] + adm;
        float v1 = as_[s1 * H + myh] + adm;
        float v2 = as_[s2 * H + myh] + adm;
        float v3 = as_[s3 * H + myh] + adm;
        v0 = v0 >= 0.f ? v0 : 0.2f * v0;
        v1 = v1 >= 0.f ? v1 : 0.2f * v1;
        v2 = v2 >= 0.f ? v2 : 0.2f * v2;
        v3 = v3 >= 0.f ? v3 : 0.2f * v3;
        float e0 = __expf(v0), e1 = __expf(v1), e2 = __expf(v2), e3 = __expf(v3);
        uint2 r0 = hf[(size_t)s0 * 32 + lane];
        uint2 r1 = hf[(size_t)s1 * 32 + lane];
        uint2 r2 = hf[(size_t)s2 * 32 + lane];
        uint2 r3 = hf[(size_t)s3 * 32 + lane];
        den += (e0 + e1) + (e2 + e3);
        float2 a0 = __half22float2(*(__half2*)&r0.x), b0 = __half22float2(*(__half2*)&r0.y);
        float2 a1 = __half22float2(*(__half2*)&r1.x), b1 = __half22float2(*(__half2*)&r1.y);
        float2 a2 = __half22float2(*(__half2*)&r2.x), b2 = __half22float2(*(__half2*)&r2.y);
        float2 a3 = __half22float2(*(__half2*)&r3.x), b3 = __half22float2(*(__half2*)&r3.y);
        acc.x += a0.x * e0 + a1.x * e1 + a2.x * e2 + a3.x * e3;
        acc.y += a0.y * e0 + a1.y * e1 + a2.y * e2 + a3.y * e3;
        acc.z += b0.x * e0 + b1.x * e1 + b2.x * e2 + b3.x * e3;
        acc.w += b0.y * e0 + b1.y * e1 + b2.y * e2 + b3.y * e3;
    }
    for (; i < end; i++) {
        int s0 = csr[i];
        float v0 = as_[s0 * H + myh] + adm;
        v0 = v0 >= 0.f ? v0 : 0.2f * v0;
        float e0 = __expf(v0);
        uint2 r0 = hf[(size_t)s0 * 32 + lane];
        float2 a0 = __half22float2(*(__half2*)&r0.x), b0 = __half22float2(*(__half2*)&r0.y);
        den += e0;
        acc.x += a0.x * e0;
        acc.y += a0.y * e0;
        acc.z += b0.x * e0;
        acc.w += b0.y * e0;
    }

    float inv = 1.f / (den + 1e-16f);
    float4 b = ((const float4*)bias)[lane];
    acc.x = acc.x * inv + b.x;
    acc.y = acc.y * inv + b.y;
    acc.z = acc.z * inv + b.z;
    acc.w = acc.w * inv + b.w;
    if (ELU) {
        acc.x = acc.x > 0.f ? acc.x : expm1f(acc.x);
        acc.y = acc.y > 0.f ? acc.y : expm1f(acc.y);
        acc.z = acc.z > 0.f ? acc.z : expm1f(acc.z);
        acc.w = acc.w > 0.f ? acc.w : expm1f(acc.w);
    }
    ((float4*)outp)[(size_t)d * 32 + lane] = acc;
}

// ---------------- launch ----------------
extern "C" void kernel_launch(void* const* d_in, const int* in_sizes, int n_in,
                              void* d_out, int out_size) {
    const float* x      = (const float*)d_in[0];
    const int*   ei     = (const int*)d_in[1];
    const float* W1     = (const float*)d_in[2];
    const float* a_src1 = (const float*)d_in[3];
    const float* a_dst1 = (const float*)d_in[4];
    const float* b1     = (const float*)d_in[5];
    const float* W2     = (const float*)d_in[6];
    const float* a_src2 = (const float*)d_in[7];
    const float* a_dst2 = (const float*)d_in[8];
    const float* b2     = (const float*)d_in[9];
    float* out = (float*)d_out;

    const int* src = ei;
    const int* dst = ei + NEDGES;

    __half* p_hh;
    float *p_feat, *p_as, *p_ad;
    int *p_cnt, *p_rp, *p_cursor, *p_bsum, *p_csr;
    __nv_bfloat16 *p_bh1, *p_bl1, *p_bh2, *p_bl2;
    cudaGetSymbolAddress((void**)&p_hh,     g_hh);
    cudaGetSymbolAddress((void**)&p_feat,   g_feat);
    cudaGetSymbolAddress((void**)&p_as,     g_as);
    cudaGetSymbolAddress((void**)&p_ad,     g_ad);
    cudaGetSymbolAddress((void**)&p_cnt,    g_cnt);
    cudaGetSymbolAddress((void**)&p_rp,     g_rp);
    cudaGetSymbolAddress((void**)&p_cursor, g_cursor);
    cudaGetSymbolAddress((void**)&p_bsum,   g_bsum);
    cudaGetSymbolAddress((void**)&p_csr,    g_csr);
    cudaGetSymbolAddress((void**)&p_bh1,    g_bhi1);
    cudaGetSymbolAddress((void**)&p_bl1,    g_blo1);
    cudaGetSymbolAddress((void**)&p_bh2,    g_bhi2);
    cudaGetSymbolAddress((void**)&p_bl2,    g_blo2);

    static cudaStream_t s_side = nullptr;
    static cudaEvent_t  ev_fork = nullptr, ev_join = nullptr;
    if (s_side == nullptr) {
        cudaStreamCreateWithFlags(&s_side, cudaStreamNonBlocking);
        cudaEventCreateWithFlags(&ev_fork, cudaEventDisableTiming);
        cudaEventCreateWithFlags(&ev_join, cudaEventDisableTiming);
        cudaFuncSetAttribute(gemm_mma_kernel<4>, cudaFuncAttributeMaxDynamicSharedMemorySize, SMEM_GTOT);
        cudaFuncSetAttribute(gemm_mma_kernel<1>, cudaFuncAttributeMaxDynamicSharedMemorySize, SMEM_GTOT);
    }

    const int NT = 256;
    int mma_blocks   = (NNODES + 127) / 128;     // 782
    int node_warps   = (NNODES * 32 + NT - 1) / NT;
    int node1_blocks = (NNODES + 1 + NT - 1) / NT;
    int edge_blocks  = (NEDGES + NT - 1) / NT;
    int scan_blocks  = (NNODES + 4095) / 4096;

    // fork
    cudaEventRecord(ev_fork, 0);
    cudaStreamWaitEvent(s_side, ev_fork, 0);

    // side: CSR build start (#1, #2)
    cudaMemsetAsync(p_cnt, 0, NNODES * sizeof(int), s_side);
    count_kernel<<<edge_blocks, NT, 0, s_side>>>(dst, p_cnt);
    scan_local_kernel<<<scan_blocks, 512, 0, s_side>>>(p_cnt, p_cnt, p_bsum);

    // main: W prep (#3) then HMMA GEMM1 (#4 -> profiled)
    prep_w_kernel<<<128, 256>>>(W1, W2, p_bh1, p_bl1, p_bh2, p_bl2);
    gemm_mma_kernel<4><<<mma_blocks, NT, SMEM_GTOT>>>(x, p_bh1, p_bl1, p_hh, NNODES,
                                                      a_src1, a_dst1, p_as, p_ad);

    // side: finish CSR (#5, #6)
    scan_add_kernel<<<node1_blocks, NT, 0, s_side>>>(p_cnt, p_bsum, p_rp, p_cursor, scan_blocks);
    scatter_kernel<<<edge_blocks, NT, 0, s_side>>>(src, dst, p_cursor, p_csr);
    cudaEventRecord(ev_join, s_side);
    cudaStreamWaitEvent(0, ev_join, 0);

    // layer 1 aggregation + ELU
    fused_agg_kernel<4, true><<<node_warps, NT>>>(p_rp, p_csr, p_as, p_ad, p_hh, b1, p_feat);

    // layer 2
    gemm_mma_kernel<1><<<mma_blocks, NT, SMEM_GTOT>>>(p_feat, p_bh2, p_bl2, p_hh, NNODES,
                                                      a_src2, a_dst2, p_as, p_ad);
    fused_agg_kernel<1, false><<<node_warps, NT>>>(p_rp, p_csr, p_as, p_ad, p_hh, b2, out);
}